// round 1
// baseline (speedup 1.0000x reference)
#include <cuda_runtime.h>
#include <cstdint>

#define T_LEN   2048
#define B_SZ    64
#define C_SZ    256
#define L_CHUNK 64
#define PITCH   68                    /* words; ==4 mod 32 and 16B-aligned -> conflict-free 128-bit smem ops */
#define NCHUNK  (T_LEN / L_CHUNK)     /* 32 */
#define ROWS    128
#define EPS     1e-8f

// Per-channel parameters: x = nS = (beta-1)*inv, y = nOff = (1-beta)*b, z = K = beta*b*norm*inv, w = b
__device__ float4 g_params[C_SZ];
__device__ float  g_beta;

// ---------------------------------------------------------------------------
// Prep: per-channel norm = sum(w^2) over (C,3), then derived constants.
// ---------------------------------------------------------------------------
__global__ void prep_kernel(const float* __restrict__ w,
                            const float* __restrict__ beta_p,
                            const float* __restrict__ b_p) {
    __shared__ float red[8];
    const int c   = blockIdx.x;
    const int tid = threadIdx.x;
    const float* wc = w + (size_t)c * (C_SZ * 3);
    float s = 0.f;
    for (int i = tid; i < C_SZ * 3; i += blockDim.x) {
        float v = wc[i];
        s = fmaf(v, v, s);
    }
    #pragma unroll
    for (int o = 16; o; o >>= 1) s += __shfl_down_sync(0xffffffffu, s, o);
    if ((tid & 31) == 0) red[tid >> 5] = s;
    __syncthreads();
    if (tid == 0) {
        float norm = red[0] + red[1] + red[2] + red[3] + red[4] + red[5] + red[6] + red[7];
        float beta = beta_p[0];
        float bb   = b_p[c];
        float inv  = 1.0f / (norm + EPS);
        float4 p;
        p.x = (beta - 1.0f) * inv;          // nS
        p.y = (1.0f - beta) * bb;           // nOff
        p.z = (beta * bb) * (norm * inv);   // K
        p.w = bb;                           // b  (n_{-1} = b)
        g_params[c] = p;
        if (c == 0) g_beta = beta;
    }
}

// ---------------------------------------------------------------------------
// Main LIF kernel. 128 blocks x 128 threads; thread owns one (b,c) sequence.
// Coalesced global I/O staged through shared memory, cp.async double-buffered.
// ---------------------------------------------------------------------------
__device__ __forceinline__ unsigned smaddr(const void* p) {
    return (unsigned)__cvta_generic_to_shared(p);
}

__global__ void __launch_bounds__(ROWS, 1)
lif_kernel(const float* __restrict__ x, float* __restrict__ out) {
    extern __shared__ float smem[];
    float* inT[2]  = { smem,                  smem + 1 * ROWS * PITCH };
    float* outT[2] = { smem + 2 * ROWS * PITCH, smem + 3 * ROWS * PITCH };

    const int row  = threadIdx.x;
    const int lane = threadIdx.x & 31;
    const int warp = threadIdx.x >> 5;
    const int seqBase = blockIdx.x * ROWS;

    const int c = (seqBase + row) & (C_SZ - 1);
    const float4 p = g_params[c];
    const float nS = p.x, nOff = p.y, K = p.z;
    const float beta = g_beta;

    // Loader geometry: each warp owns 32 rows; one cp.async.128 per 2 rows.
    const int lr0  = warp * 32 + (lane >> 4);   // row base, advances by 2 each iter
    const int lcol = (lane & 15) * 4;           // word offset within row

    // Prefetch chunks 0 and 1
    #pragma unroll
    for (int pk = 0; pk < 2; pk++) {
        const float* gbase = x + (size_t)seqBase * T_LEN + pk * L_CHUNK;
        float* sbase = inT[pk];
        #pragma unroll
        for (int i = 0; i < 16; i++) {
            const int r = lr0 + i * 2;
            unsigned d = smaddr(sbase + r * PITCH + lcol);
            const float* s = gbase + (size_t)r * T_LEN + lcol;
            asm volatile("cp.async.cg.shared.global [%0], [%1], 16;\n" :: "r"(d), "l"(s));
        }
        asm volatile("cp.async.commit_group;\n");
    }

    // Recurrence state: n = -mthr. n_{-1} = b, spk_{-1} = 0.
    float n = p.w;
    unsigned mask = (unsigned)(__float_as_int(n) >> 31);   // == 0 (b >= 0)

    for (int k = 0; k < NCHUNK; k++) {
        const int buf = k & 1;
        // One group committed per iteration (possibly empty) => wait_group 1
        // always leaves exactly groups 0..k complete (chunk k ready).
        asm volatile("cp.async.wait_group 1;\n");
        __syncthreads();

        // ---- serial compute: 64 steps, 14-cycle chain per step ----
        {
            const float* tin = inT[buf] + row * PITCH;
            float* tout      = outT[buf] + row * PITCH;
            #pragma unroll
            for (int j = 0; j < L_CHUNK; j += 4) {
                const float4 xv = *(const float4*)(tin + j);
                float4 sv;
                #define LIF_STEP(XX, SS) do {                                        \
                    float eA = fmaf((XX), nS, nOff);                                 \
                    float eB = eA + K;                                               \
                    unsigned ea  = __float_as_uint(eA);                              \
                    unsigned sel = ea ^ ((ea ^ __float_as_uint(eB)) & mask);         \
                    n = fmaf(beta, n, __uint_as_float(sel));                         \
                    mask = (unsigned)(__float_as_int(n) >> 31);                      \
                    (SS) = __uint_as_float(0x3F800000u & mask);                      \
                } while (0)
                LIF_STEP(xv.x, sv.x);
                LIF_STEP(xv.y, sv.y);
                LIF_STEP(xv.z, sv.z);
                LIF_STEP(xv.w, sv.w);
                #undef LIF_STEP
                *(float4*)(tout + j) = sv;
            }
        }
        __syncthreads();

        // ---- prefetch chunk k+2 into the buffer we just consumed ----
        if (k + 2 < NCHUNK) {
            const float* gbase = x + (size_t)seqBase * T_LEN + (k + 2) * L_CHUNK;
            float* sbase = inT[buf];
            #pragma unroll
            for (int i = 0; i < 16; i++) {
                const int r = lr0 + i * 2;
                unsigned d = smaddr(sbase + r * PITCH + lcol);
                const float* s = gbase + (size_t)r * T_LEN + lcol;
                asm volatile("cp.async.cg.shared.global [%0], [%1], 16;\n" :: "r"(d), "l"(s));
            }
        }
        asm volatile("cp.async.commit_group;\n");

        // ---- coalesced store of the spike tile ----
        {
            const float* sbase = outT[buf];
            float* gbase = out + (size_t)seqBase * T_LEN + k * L_CHUNK;
            #pragma unroll
            for (int i = 0; i < 16; i++) {
                const int r = lr0 + i * 2;
                const float4 v = *(const float4*)(sbase + r * PITCH + lcol);
                *(float4*)(gbase + (size_t)r * T_LEN + lcol) = v;
            }
        }
    }
}

// ---------------------------------------------------------------------------
extern "C" void kernel_launch(void* const* d_in, const int* in_sizes, int n_in,
                              void* d_out, int out_size) {
    const float* x    = (const float*)d_in[0];   // (B, C, T)
    const float* w    = (const float*)d_in[1];   // (C, C, 3)
    const float* beta = (const float*)d_in[2];   // (1,)
    const float* b    = (const float*)d_in[3];   // (C,)
    float* out = (float*)d_out;                  // (B, C, T)

    prep_kernel<<<C_SZ, 256>>>(w, beta, b);

    const size_t smem_bytes = (size_t)4 * ROWS * PITCH * sizeof(float);  // 139264
    cudaFuncSetAttribute(lif_kernel, cudaFuncAttributeMaxDynamicSharedMemorySize,
                         (int)smem_bytes);
    lif_kernel<<<(B_SZ * C_SZ) / ROWS, ROWS, smem_bytes>>>(x, out);
}

// round 2
// speedup vs baseline: 1.2909x; 1.2909x over previous
#include <cuda_runtime.h>
#include <cstdint>

#define T_LEN   2048
#define B_SZ    64
#define C_SZ    256
#define L_CHUNK 64
#define PITCH   68                    /* words; ==4 mod 32, 16B aligned -> conflict-free LDS.128 */
#define NCHUNK  (T_LEN / L_CHUNK)     /* 32 */
#define ROWS    128
#define DEPTH   3
#define EPS     1e-8f

// Per-channel parameters: x = nS = (beta-1)*inv, y = nOff = (1-beta)*b, z = K = beta*b*norm*inv, w = b
__device__ float4 g_params[C_SZ];
__device__ float  g_beta;

// ---------------------------------------------------------------------------
// Prep: per-channel norm = sum(w^2) over (C,3), then derived constants.
// ---------------------------------------------------------------------------
__global__ void prep_kernel(const float* __restrict__ w,
                            const float* __restrict__ beta_p,
                            const float* __restrict__ b_p) {
    __shared__ float red[8];
    const int c   = blockIdx.x;
    const int tid = threadIdx.x;
    const float* wc = w + (size_t)c * (C_SZ * 3);
    float s = 0.f;
    for (int i = tid; i < C_SZ * 3; i += blockDim.x) {
        float v = wc[i];
        s = fmaf(v, v, s);
    }
    #pragma unroll
    for (int o = 16; o; o >>= 1) s += __shfl_down_sync(0xffffffffu, s, o);
    if ((tid & 31) == 0) red[tid >> 5] = s;
    __syncthreads();
    if (tid == 0) {
        float norm = red[0] + red[1] + red[2] + red[3] + red[4] + red[5] + red[6] + red[7];
        float beta = beta_p[0];
        float bb   = b_p[c];
        float inv  = 1.0f / (norm + EPS);
        float4 p;
        p.x = (beta - 1.0f) * inv;          // nS
        p.y = (1.0f - beta) * bb;           // nOff
        p.z = (beta * bb) * (norm * inv);   // K
        p.w = bb;                           // b  (n_{-1} = b)
        g_params[c] = p;
        if (c == 0) g_beta = beta;
    }
}

// ---------------------------------------------------------------------------
__device__ __forceinline__ unsigned smaddr(const void* p) {
    return (unsigned)__cvta_generic_to_shared(p);
}

// n-space LIF: n_t = beta*n_{t-1} + eA_t + K*spk_{t-1},  eA_t = x_t*nS + nOff,
// spk_t = (n_t < 0).  n_true >= n_lin since K >= 0, so the linear scan's
// negative set is a superset of true spikes -> fast linear path + rare redo.
__global__ void __launch_bounds__(ROWS, 1)
lif_kernel(const float* __restrict__ x, float* __restrict__ out) {
    extern __shared__ float smem[];
    float* b0 = smem;
    float* b1 = smem + 1 * ROWS * PITCH;
    float* b2 = smem + 2 * ROWS * PITCH;

    const int row  = threadIdx.x;
    const int lane = threadIdx.x & 31;
    const int warp = threadIdx.x >> 5;
    const int seqBase = blockIdx.x * ROWS;

    const int c = (seqBase + row) & (C_SZ - 1);
    const float4 p = g_params[c];
    const float nS = p.x, nOff = p.y, K = p.z;
    const float beta = g_beta;

    // Loader geometry: each warp owns its own 32 rows; one 16B cp.async per 2 rows.
    const int lr0  = warp * 32 + (lane >> 4);
    const int lcol = (lane & 15) * 4;

    // Prefetch chunks 0..DEPTH-1
    {
        float* bufs[DEPTH] = { b0, b1, b2 };
        #pragma unroll
        for (int pk = 0; pk < DEPTH; pk++) {
            const float* gbase = x + (size_t)seqBase * T_LEN + pk * L_CHUNK;
            float* sbase = bufs[pk];
            #pragma unroll
            for (int i = 0; i < 16; i++) {
                const int r = lr0 + i * 2;
                unsigned d = smaddr(sbase + r * PITCH + lcol);
                const float* s = gbase + (size_t)r * T_LEN + lcol;
                asm volatile("cp.async.cg.shared.global [%0], [%1], 16;\n" :: "r"(d), "l"(s));
            }
            asm volatile("cp.async.commit_group;\n");
        }
    }

    float n = p.w;          // n_{-1} = b >= 0
    unsigned mask = 0u;     // spk_{-1} = 0 (0 or 0xFFFFFFFF)

    #pragma unroll 1
    for (int k = 0; k < NCHUNK; k++) {
        float* tile = b0;   // rotate at loop end

        // One commit per iteration => wait_group DEPTH-1 leaves chunk k complete.
        asm volatile("cp.async.wait_group %0;\n" :: "n"(DEPTH - 1));
        __syncwarp();

        const float* tin = tile + row * PITCH;
        const float n0  = n;
        const unsigned m0 = mask;

        // ---- fast linear path: 4-cycle FFMA chain, sign bits OR'd off-chain ----
        float nl = n0;
        unsigned flag = 0u;
        #pragma unroll
        for (int j = 0; j < L_CHUNK; j += 4) {
            const float4 xv = *(const float4*)(tin + j);
            float e;
            e = fmaf(xv.x, nS, nOff); nl = fmaf(beta, nl, e); flag |= __float_as_uint(nl);
            e = fmaf(xv.y, nS, nOff); nl = fmaf(beta, nl, e); flag |= __float_as_uint(nl);
            e = fmaf(xv.z, nS, nOff); nl = fmaf(beta, nl, e); flag |= __float_as_uint(nl);
            e = fmaf(xv.w, nS, nOff); nl = fmaf(beta, nl, e); flag |= __float_as_uint(nl);
        }
        const unsigned needs = (flag | m0) >> 31;
        const unsigned bal = __ballot_sync(0xffffffffu, needs);

        if (bal == 0) {
            n = nl; mask = 0u;
        } else if (needs) {
            // ---- rare exact redo with full LIF, direct per-lane spike store ----
            float nn = n0;
            unsigned mm = m0;
            float* gout = out + (size_t)(seqBase + row) * T_LEN + k * L_CHUNK;
            #pragma unroll 4
            for (int j = 0; j < L_CHUNK; j += 4) {
                const float4 xv = *(const float4*)(tin + j);
                float4 sv;
                #define LIF_STEP(XX, SS) do {                                        \
                    float eA = fmaf((XX), nS, nOff);                                 \
                    float eB = eA + K;                                               \
                    unsigned ea  = __float_as_uint(eA);                              \
                    unsigned sel = ea ^ ((ea ^ __float_as_uint(eB)) & mm);           \
                    nn = fmaf(beta, nn, __uint_as_float(sel));                       \
                    mm = (unsigned)(__float_as_int(nn) >> 31);                       \
                    (SS) = __uint_as_float(0x3F800000u & mm);                        \
                } while (0)
                LIF_STEP(xv.x, sv.x);
                LIF_STEP(xv.y, sv.y);
                LIF_STEP(xv.z, sv.z);
                LIF_STEP(xv.w, sv.w);
                #undef LIF_STEP
                *(float4*)(gout + j) = sv;
            }
            n = nn; mask = mm;
        } else {
            n = nl; mask = 0u;
        }
        __syncwarp();   // all tile reads done before the buffer is refilled

        // ---- prefetch chunk k+DEPTH into the buffer just consumed ----
        if (k + DEPTH < NCHUNK) {
            const float* gbase = x + (size_t)seqBase * T_LEN + (k + DEPTH) * L_CHUNK;
            #pragma unroll
            for (int i = 0; i < 16; i++) {
                const int r = lr0 + i * 2;
                unsigned d = smaddr(tile + r * PITCH + lcol);
                const float* s = gbase + (size_t)r * T_LEN + lcol;
                asm volatile("cp.async.cg.shared.global [%0], [%1], 16;\n" :: "r"(d), "l"(s));
            }
        }
        asm volatile("cp.async.commit_group;\n");

        // ---- coalesced zero stores (skip rows rewritten by redo lanes) ----
        {
            float* gbase = out + (size_t)seqBase * T_LEN + k * L_CHUNK;
            const float4 z = make_float4(0.f, 0.f, 0.f, 0.f);
            if (bal == 0) {
                #pragma unroll
                for (int i = 0; i < 16; i++) {
                    const int r = lr0 + i * 2;
                    *(float4*)(gbase + (size_t)r * T_LEN + lcol) = z;
                }
            } else {
                #pragma unroll
                for (int i = 0; i < 16; i++) {
                    const int r  = lr0 + i * 2;
                    const int rl = (lane >> 4) + i * 2;     // owner lane of row r
                    if (!((bal >> rl) & 1u))
                        *(float4*)(gbase + (size_t)r * T_LEN + lcol) = z;
                }
            }
        }

        // rotate buffers
        float* t0 = b0; b0 = b1; b1 = b2; b2 = t0;
    }
}

// ---------------------------------------------------------------------------
extern "C" void kernel_launch(void* const* d_in, const int* in_sizes, int n_in,
                              void* d_out, int out_size) {
    const float* x    = (const float*)d_in[0];   // (B, C, T)
    const float* w    = (const float*)d_in[1];   // (C, C, 3)
    const float* beta = (const float*)d_in[2];   // (1,)
    const float* b    = (const float*)d_in[3];   // (C,)
    float* out = (float*)d_out;                  // (B, C, T)

    prep_kernel<<<C_SZ, 256>>>(w, beta, b);

    const size_t smem_bytes = (size_t)DEPTH * ROWS * PITCH * sizeof(float);  // 104448
    cudaFuncSetAttribute(lif_kernel, cudaFuncAttributeMaxDynamicSharedMemorySize,
                         (int)smem_bytes);
    lif_kernel<<<(B_SZ * C_SZ) / ROWS, ROWS, smem_bytes>>>(x, out);
}